// round 15
// baseline (speedup 1.0000x reference)
#include <cuda_runtime.h>
#include <cuda_fp16.h>
#include <cstdint>

// Problem constants (fixed by dataset: B=4, S=2048, D=1024, H=16)
#define B_  4
#define S_  2048
#define D_  1024
#define H_  16
#define DK_ 64
#define M_  (B_ * S_)   // 8192
#define DD_ ((size_t)D_ * D_)

// ---------------------------------------------------------------------------
// Device-global scratch
// ---------------------------------------------------------------------------
__device__ __half g_Xh [(size_t)M_ * D_];          // X fp16   [b*2048+s][d]
__device__ __half g_XhT[(size_t)M_ * D_];          // X^T fp16 [b][d][s]
__device__ __half g_Wvh[DD_];                      // Wv hi
__device__ __half g_Ghh[(size_t)B_ * DD_];         // Gram hi  [b][i][j]
__device__ float  g_A  [(size_t)B_ * DD_];         // A = G @ Wv^T  [b][j][n]
__device__ float  g_Tp [(size_t)B_ * H_ * 4 * DK_ * DK_];  // T split-K partials
__device__ __half g_UhT[(size_t)B_ * DD_];         // U^T hi   [b][n][j]
__device__ int    g_flags[M_];                     // per (b,q) row: mask has a 0

// Lower-triangle block enumeration for the symmetric Gram (8x8 blocks of 128)
__device__ __constant__ int GBI[36] =
    {0,1,1,2,2,2,3,3,3,3,4,4,4,4,4,5,5,5,5,5,5,
     6,6,6,6,6,6,6,7,7,7,7,7,7,7,7};
__device__ __constant__ int GBJ[36] =
    {0,0,1,0,1,2,0,1,2,3,0,1,2,3,4,0,1,2,3,4,5,
     0,1,2,3,4,5,6,0,1,2,3,4,5,6,7};

// ---------------------------------------------------------------------------
// Helpers
// ---------------------------------------------------------------------------
__device__ __forceinline__ uint32_t smem_u32(const void* p) {
    uint32_t a;
    asm("{ .reg .u64 t; cvta.to.shared.u64 t, %1; cvt.u32.u64 %0, t; }"
        : "=r"(a) : "l"(p));
    return a;
}
__device__ __forceinline__ void cp16(uint32_t saddr, const void* gptr) {
    asm volatile("cp.async.ca.shared.global [%0], [%1], 16;"
                 :: "r"(saddr), "l"(gptr) : "memory");
}
__device__ __forceinline__ void cp_commit() {
    asm volatile("cp.async.commit_group;" ::: "memory");
}
template <int N>
__device__ __forceinline__ void cp_wait() {
    asm volatile("cp.async.wait_group %0;" :: "n"(N) : "memory");
}
__device__ __forceinline__ void ldsm4(uint32_t* r, uint32_t addr) {
    asm volatile("ldmatrix.sync.aligned.m8n8.x4.shared.b16 {%0,%1,%2,%3}, [%4];"
                 : "=r"(r[0]), "=r"(r[1]), "=r"(r[2]), "=r"(r[3]) : "r"(addr));
}
__device__ __forceinline__ void mma16816(float* d, const uint32_t* a,
                                         uint32_t b0, uint32_t b1) {
    asm volatile(
        "mma.sync.aligned.m16n8k16.row.col.f32.f16.f16.f32 "
        "{%0,%1,%2,%3}, {%4,%5,%6,%7}, {%8,%9}, {%0,%1,%2,%3};"
        : "+f"(d[0]), "+f"(d[1]), "+f"(d[2]), "+f"(d[3])
        : "r"(a[0]), "r"(a[1]), "r"(a[2]), "r"(a[3]), "r"(b0), "r"(b1));
}

// ---------------------------------------------------------------------------
// Mega-prep kernel. grid (16, 32, 21), 256 threads.
//  z 0..3  : x fp32 -> g_Xh + g_XhT (64x64 tile per block, batch = z)
//  z == 4  : Wv fp32 -> fp16 hi      (512 blocks x 2 float4 / thread)
//  z 5..20 : mask row scan -> g_flags (512 blocks per z, 1 row per block)
// ---------------------------------------------------------------------------
__global__ __launch_bounds__(256) void prep_all(const float* __restrict__ x,
                                                const float* __restrict__ wv,
                                                const int* __restrict__ mask)
{
    __shared__ __half t[64][72];
    int tid = threadIdx.x;
    int z = blockIdx.z;

    if (z < 4) {
        int d0 = blockIdx.x * 64, s0 = blockIdx.y * 64, b = z;
        int rr = tid >> 4;
        int cc = (tid & 15) * 4;
#pragma unroll
        for (int pass = 0; pass < 4; pass++) {
            int r = rr + pass * 16;
            size_t go = ((size_t)b * 2048 + s0 + r) * D_ + d0 + cc;
            float4 v = *(const float4*)(x + go);
            __half h0 = __float2half_rn(v.x), h1 = __float2half_rn(v.y);
            __half h2 = __float2half_rn(v.z), h3 = __float2half_rn(v.w);
            __half2 p0 = __halves2half2(h0, h1), p1 = __halves2half2(h2, h3);
            uint2 pk;
            pk.x = *(uint32_t*)&p0; pk.y = *(uint32_t*)&p1;
            *(uint2*)(&g_Xh[go]) = pk;
            t[cc + 0][r] = h0; t[cc + 1][r] = h1;
            t[cc + 2][r] = h2; t[cc + 3][r] = h3;
        }
        __syncthreads();
#pragma unroll
        for (int pass = 0; pass < 4; pass++) {
            int dr = rr + pass * 16;
            __half2 q0 = __halves2half2(t[dr][cc + 0], t[dr][cc + 1]);
            __half2 q1 = __halves2half2(t[dr][cc + 2], t[dr][cc + 3]);
            uint2 pk;
            pk.x = *(uint32_t*)&q0; pk.y = *(uint32_t*)&q1;
            *(uint2*)(&g_XhT[(size_t)b * D_ * 2048 +
                             (size_t)(d0 + dr) * 2048 + s0 + cc]) = pk;
        }
    } else if (z == 4) {
        int blk = blockIdx.y * 16 + blockIdx.x;        // 0..511
#pragma unroll
        for (int u = 0; u < 2; u++) {
            int i = blk * 512 + tid * 2 + u;           // float4 index < 262144
            float4 v = ((const float4*)wv)[i];
            __half2* hp = (__half2*)g_Wvh + (size_t)i * 2;
            hp[0] = __halves2half2(__float2half_rn(v.x), __float2half_rn(v.y));
            hp[1] = __halves2half2(__float2half_rn(v.z), __float2half_rn(v.w));
        }
    } else {
        int row = (z - 5) * 512 + blockIdx.y * 16 + blockIdx.x;  // 0..8191
        const int4* m4 = (const int4*)(mask + (size_t)row * S_);
        bool zf = false;
#pragma unroll
        for (int it = 0; it < 2; it++) {
            int4 v = m4[tid + it * 256];
            zf |= (v.x == 0) | (v.y == 0) | (v.z == 0) | (v.w == 0);
        }
        int any = __syncthreads_or(zf);
        if (tid == 0) g_flags[row] = any;
    }
}

// ---------------------------------------------------------------------------
// Symmetric Gram kernel: Ghh_b = fp16(XhT_b @ XhT_b^T), lower-triangle tiles.
// 128x128 tile, BK=64, K=2048, 8 warps (2m x 4n, 64x32 each), 3-stage cp.async.
// grid = (36, 1, 4) = 144 CTAs (one full wave). Coalesced mirror writes.
// ---------------------------------------------------------------------------
#define GPAD    144
#define G_AB    (128 * GPAD)          // 18432
#define G_STAGE (2 * G_AB)            // 36864
#define G_SMEM  (3 * G_STAGE)         // 110592

__global__ __launch_bounds__(256, 1) void gram_sym()
{
    extern __shared__ char dsm[];
    const uint32_t sbase = smem_u32(dsm);

    const int tid  = threadIdx.x;
    const int lane = tid & 31;
    const int wid  = tid >> 5;
    const int wm   = wid & 1;
    const int wn   = wid >> 1;
    const int b    = blockIdx.z;
    const int bi   = GBI[blockIdx.x];
    const int bj   = GBJ[blockIdx.x];

    const __half* A0 = g_XhT + (size_t)b * D_ * 2048 + (size_t)bi * 128 * 2048;
    const __half* B0 = g_XhT + (size_t)b * D_ * 2048 + (size_t)bj * 128 * 2048;

    auto load_chunk = [&](int buf, int k0) {
        uint32_t st = sbase + buf * G_STAGE;
#pragma unroll
        for (int it = 0; it < 4; it++) {
            int sidx = tid + it * 256;
            int r = sidx >> 3, s = sidx & 7;
            cp16(st + r * GPAD + s * 16,        A0 + (size_t)r * 2048 + k0 + s * 8);
            cp16(st + G_AB + r * GPAD + s * 16, B0 + (size_t)r * 2048 + k0 + s * 8);
        }
    };

    float acc[4][4][4];
#pragma unroll
    for (int mt = 0; mt < 4; mt++)
#pragma unroll
        for (int nt = 0; nt < 4; nt++)
#pragma unroll
            for (int e = 0; e < 4; e++) acc[mt][nt][e] = 0.f;

    load_chunk(0, 0);   cp_commit();
    load_chunk(1, 64);  cp_commit();

    const int arow  = lane & 15;
    const int aksel = lane >> 4;
    const int brow  = (lane & 7) + 8 * ((lane >> 3) & 1);
    const int bksel = lane >> 4;
    const int NC = 2048 >> 6;

    for (int c = 0; c < NC; c++) {
        const int buf = c % 3;
        cp_wait<1>();
        __syncthreads();
        if (c + 2 < NC) load_chunk((c + 2) % 3, (c + 2) * 64);
        cp_commit();

        const uint32_t st = sbase + buf * G_STAGE;
#pragma unroll
        for (int ks = 0; ks < 4; ks++) {
            const int k0 = ks * 16;
            uint32_t af[4][4], bf[2][4];
#pragma unroll
            for (int mt = 0; mt < 4; mt++) {
                uint32_t ad = st + (wm * 64 + mt * 16 + arow) * GPAD
                            + (k0 + aksel * 8) * 2;
                ldsm4(af[mt], ad);
            }
#pragma unroll
            for (int ng = 0; ng < 2; ng++) {
                uint32_t bd = st + G_AB
                            + (wn * 32 + ng * 16 + brow) * GPAD
                            + (k0 + bksel * 8) * 2;
                ldsm4(bf[ng], bd);
            }
#pragma unroll
            for (int mt = 0; mt < 4; mt++)
#pragma unroll
                for (int nt = 0; nt < 4; nt++) {
                    const int ng = nt >> 1, w = nt & 1;
                    mma16816(acc[mt][nt], af[mt], bf[ng][w], bf[ng][w + 2]);
                }
        }
    }

    // Stage fp16 tile in smem (row stride 136 halves = 272B)
    __syncthreads();
    __half* tile = (__half*)dsm;
#pragma unroll
    for (int mt = 0; mt < 4; mt++)
#pragma unroll
        for (int nt = 0; nt < 4; nt++)
#pragma unroll
            for (int hr = 0; hr < 2; hr++) {
                int r = wm * 64 + mt * 16 + (lane >> 2) + hr * 8;
                int col = wn * 32 + nt * 8 + (lane & 3) * 2;
                *(__half2*)&tile[r * 136 + col] = __halves2half2(
                    __float2half_rn(acc[mt][nt][hr * 2 + 0]),
                    __float2half_rn(acc[mt][nt][hr * 2 + 1]));
            }
    __syncthreads();

    __half* Gb = g_Ghh + (size_t)b * DD_;
    // Direct write: block (bi, bj), coalesced uint4 (8 halves) per access
    for (int e = tid; e < 128 * 16; e += 256) {
        int r = e >> 4, q = e & 15;
        *(uint4*)(Gb + (size_t)(bi * 128 + r) * 1024 + bj * 128 + q * 8) =
            *(uint4*)&tile[r * 136 + q * 8];
    }
    // Mirror write: block (bj, bi) = transpose, row-owned coalesced stores.
    // Thread tid handles row j = tid>>1, columns [ihalf, ihalf+64).
    if (bi != bj) {
        int j = tid >> 1, ihalf = (tid & 1) * 64;
        __half* rowp = Gb + (size_t)(bj * 128 + j) * 1024 + bi * 128 + ihalf;
#pragma unroll
        for (int g = 0; g < 8; g++) {
            __half tmp[8];
#pragma unroll
            for (int e = 0; e < 8; e++)
                tmp[e] = tile[(ihalf + g * 8 + e) * 136 + j];
            *(uint4*)(rowp + g * 8) = *(uint4*)tmp;
        }
    }
}

// ---------------------------------------------------------------------------
// Big-tile single-term HMMA GEMM: C = A0 @ B0^T, fp16 in, fp32/fp16 out.
// BM=128 BN=256 BK=64, 3-stage cp.async, 256 threads, 8 warps 2m x 4n (64x64).
// ---------------------------------------------------------------------------
#define BTPAD      144
#define BT_A_BYTES (128 * BTPAD)
#define BT_B_BYTES (256 * BTPAD)
#define BT_STAGE   (BT_A_BYTES + BT_B_BYTES)
#define BT_SMEM    (3 * BT_STAGE)           // 165888

template <bool HALFC>
__global__ __launch_bounds__(256, 1) void hgemm_bt(
    const __half* __restrict__ A0p, const __half* __restrict__ B0p,
    float* __restrict__ Cp, __half* __restrict__ ChP,
    int K, int lda, int ldb, int ldc,
    size_t aZ, size_t bZ, size_t cZ)
{
    extern __shared__ char dsm[];
    const uint32_t sbase = smem_u32(dsm);

    const int tid  = threadIdx.x;
    const int lane = tid & 31;
    const int wid  = tid >> 5;
    const int wm   = wid & 1;
    const int wn   = wid >> 1;
    const int z    = blockIdx.z;
    const int m0   = blockIdx.y * 128;
    const int n0   = blockIdx.x * 256;

    const __half* A0 = A0p + z * aZ + (size_t)m0 * lda;
    const __half* B0 = B0p + z * bZ + (size_t)n0 * ldb;

    auto load_chunk = [&](int buf, int k0) {
        uint32_t st = sbase + buf * BT_STAGE;
#pragma unroll
        for (int it = 0; it < 4; it++) {
            int sidx = tid + it * 256;
            int r = sidx >> 3, s = sidx & 7;
            cp16(st + r * BTPAD + s * 16, A0 + (size_t)r * lda + k0 + s * 8);
        }
#pragma unroll
        for (int it = 0; it < 8; it++) {
            int sidx = tid + it * 256;
            int r = sidx >> 3, s = sidx & 7;
            cp16(st + BT_A_BYTES + r * BTPAD + s * 16,
                 B0 + (size_t)r * ldb + k0 + s * 8);
        }
    };

    float acc[4][8][4];
#pragma unroll
    for (int mt = 0; mt < 4; mt++)
#pragma unroll
        for (int nt = 0; nt < 8; nt++)
#pragma unroll
            for (int e = 0; e < 4; e++) acc[mt][nt][e] = 0.f;

    load_chunk(0, 0);   cp_commit();
    load_chunk(1, 64);  cp_commit();

    const int arow  = lane & 15;
    const int aksel = lane >> 4;
    const int brow  = (lane & 7) + 8 * ((lane >> 3) & 1);
    const int bksel = lane >> 4;
    const int NC = K >> 6;

    for (int c = 0; c < NC; c++) {
        const int buf = c % 3;
        cp_wait<1>();
        __syncthreads();
        if (c + 2 < NC) load_chunk((c + 2) % 3, (c + 2) * 64);
        cp_commit();

        const uint32_t st = sbase + buf * BT_STAGE;
#pragma unroll
        for (int ks = 0; ks < 4; ks++) {
            const int k0 = ks * 16;
            uint32_t af[4][4], bf[4][4];
#pragma unroll
            for (int mt = 0; mt < 4; mt++) {
                uint32_t ad = st + (wm * 64 + mt * 16 + arow) * BTPAD
                            + (k0 + aksel * 8) * 2;
                ldsm4(af[mt], ad);
            }
#pragma unroll
            for (int ng = 0; ng < 4; ng++) {
                uint32_t bd = st + BT_A_BYTES
                            + (wn * 64 + ng * 16 + brow) * BTPAD
                            + (k0 + bksel * 8) * 2;
                ldsm4(bf[ng], bd);
            }
#pragma unroll
            for (int mt = 0; mt < 4; mt++)
#pragma unroll
                for (int nt = 0; nt < 8; nt++) {
                    const int ng = nt >> 1, w = nt & 1;
                    mma16816(acc[mt][nt], af[mt], bf[ng][w], bf[ng][w + 2]);
                }
        }
    }

    if (HALFC) {
        __half* Ch = ChP + z * cZ;
#pragma unroll
        for (int mt = 0; mt < 4; mt++) {
            const int rbase = m0 + wm * 64 + mt * 16 + (lane >> 2);
#pragma unroll
            for (int nt = 0; nt < 8; nt++) {
                const int col = n0 + wn * 64 + nt * 8 + (lane & 3) * 2;
#pragma unroll
                for (int hr = 0; hr < 2; hr++) {
                    size_t off = (size_t)(rbase + hr * 8) * ldc + col;
                    *(__half2*)(Ch + off) = __halves2half2(
                        __float2half_rn(acc[mt][nt][hr * 2 + 0]),
                        __float2half_rn(acc[mt][nt][hr * 2 + 1]));
                }
            }
        }
    } else {
        float* C = Cp + z * cZ;
#pragma unroll
        for (int mt = 0; mt < 4; mt++) {
            const int rbase = m0 + wm * 64 + mt * 16 + (lane >> 2);
#pragma unroll
            for (int nt = 0; nt < 8; nt++) {
                const int col = n0 + wn * 64 + nt * 8 + (lane & 3) * 2;
                *(float2*)(C + (size_t)rbase * ldc + col) =
                    make_float2(acc[mt][nt][0], acc[mt][nt][1]);
                *(float2*)(C + (size_t)(rbase + 8) * ldc + col) =
                    make_float2(acc[mt][nt][2], acc[mt][nt][3]);
            }
        }
    }
}

// ---------------------------------------------------------------------------
// Kernel: split-K partials of T_bh = Wk_h @ A_b[:, h*64:+64]
// cp.async double-buffered (R14-proven).
// ---------------------------------------------------------------------------
#define TPADF   68
#define T_MAT   (64 * TPADF * 4)        // 17408 B per matrix
#define T_STAGE (2 * T_MAT)
#define T_SMEM  (2 * T_STAGE)           // 69632 B

__global__ __launch_bounds__(256) void t_kernel3(const float* __restrict__ wk)
{
    extern __shared__ char dsm[];
    const uint32_t sbase = smem_u32(dsm);
    int bh = blockIdx.x, sp = blockIdx.y;
    int b = bh >> 4, h = bh & 15;
    int tid = threadIdx.x, ti = tid >> 4, tj = tid & 15;

    const float* wkh = wk + (size_t)(h * 64) * D_;
    const float* Ab  = g_A + (size_t)b * DD_ + h * 64;

    auto load_tiles = [&](int stage, int j0) {
        uint32_t st = sbase + stage * T_STAGE;
#pragma unroll
        for (int it = 0; it < 4; it++) {
            int sidx = tid + it * 256;
            int r = sidx >> 4, s = sidx & 15;
            cp16(st + r * (TPADF * 4) + s * 16,
                 wkh + (size_t)r * D_ + j0 + s * 4);
            cp16(st + T_MAT + r * (TPADF * 4) + s * 16,
                 Ab + (size_t)(j0 + r) * D_ + s * 4);
        }
    };

    float acc[4][4] = {};
    load_tiles(0, sp * 256);
    cp_commit();

    for (int it = 0; it < 4; it++) {
        cp_wait<0>();
        __syncthreads();
        if (it + 1 < 4) load_tiles((it + 1) & 1, sp * 256 + (it + 1) * 64);
        cp_commit();

        const float* K_s = (const float*)(dsm + (it & 1) * T_STAGE);
        const float* A_s = (const float*)(dsm + (it & 1) * T_STAGE + T_MAT);
#pragma unroll 8
        for (int j = 0; j < 64; j++) {
            float kr[4], ar[4];
#pragma unroll
            for (int i = 0; i < 4; i++) kr[i] = K_s[(ti * 4 + i) * TPADF + j];
#pragma unroll
            for (int c = 0; c < 4; c++) ar[c] = A_s[j * TPADF + tj * 4 + c];
#pragma unroll
            for (int i = 0; i < 4; i++)
#pragma unroll
                for (int c = 0; c < 4; c++)
                    acc[i][c] = fmaf(kr[i], ar[c], acc[i][c]);
        }
        __syncthreads();
    }
#pragma unroll
    for (int i = 0; i < 4; i++)
#pragma unroll
        for (int c = 0; c < 4; c++)
            g_Tp[((size_t)bh * 4 + sp) * 4096 + (ti * 4 + i) * 64 + tj * 4 + c]
                = acc[i][c];
}

// ---------------------------------------------------------------------------
// Kernel: U^T[b][h*64+c][j] = (1/8) sum_r Wq[h*64+r][j] T_bh[r][c] (fp16 hi)
// cp.async double-buffered Wq tiles (R14-proven).
// ---------------------------------------------------------------------------
#define U_SMEM  (T_MAT + 2 * T_MAT)     // 52224 B

__global__ __launch_bounds__(256) void u_kernel3(const float* __restrict__ wq)
{
    extern __shared__ char dsm[];
    const uint32_t sbase = smem_u32(dsm);
    int bh = blockIdx.x, slice = blockIdx.y;
    int b = bh >> 4, h = bh & 15;
    int tid = threadIdx.x, ti = tid >> 4, tj = tid & 15;

    float* T_s = (float*)dsm;
    const float* wqh = wq + (size_t)(h * 64) * D_;

    auto load_w = [&](int stage, int j0) {
        uint32_t st = sbase + T_MAT + stage * T_MAT;
#pragma unroll
        for (int it = 0; it < 4; it++) {
            int sidx = tid + it * 256;
            int r = sidx >> 4, s = sidx & 15;
            cp16(st + r * (TPADF * 4) + s * 16,
                 wqh + (size_t)r * D_ + j0 + s * 4);
        }
    };

    load_w(0, slice * 256);
    cp_commit();

    const float* Tp = g_Tp + (size_t)bh * 4 * 4096;
    for (int e = tid; e < 4096; e += 256) {
        float s = Tp[e] + Tp[e + 4096] + Tp[e + 8192] + Tp[e + 12288];
        T_s[(e >> 6) * TPADF + (e & 63)] = s;
    }

    for (int ch = 0; ch < 4; ch++) {
        int j0 = slice * 256 + ch * 64;
        cp_wait<0>();
        __syncthreads();
        if (ch + 1 < 4) load_w((ch + 1) & 1, slice * 256 + (ch + 1) * 64);
        cp_commit();

        const float* W_s = (const float*)(dsm + T_MAT + (ch & 1) * T_MAT);
        float acc[4][4] = {};
#pragma unroll 8
        for (int r = 0; r < 64; r++) {
            float tr[4], wr[4];
#pragma unroll
            for (int i = 0; i < 4; i++) tr[i] = T_s[r * TPADF + ti * 4 + i];
#pragma unroll
            for (int j = 0; j < 4; j++) wr[j] = W_s[r * TPADF + tj * 4 + j];
#pragma unroll
            for (int i = 0; i < 4; i++)
#pragma unroll
                for (int j = 0; j < 4; j++)
                    acc[i][j] = fmaf(tr[i], wr[j], acc[i][j]);
        }
#pragma unroll
        for (int i = 0; i < 4; i++) {
            int c = ti * 4 + i;
            size_t off = (size_t)b * DD_ + (size_t)(h * 64 + c) * D_ + j0 + tj * 4;
#pragma unroll
            for (int j = 0; j < 4; j += 2) {
                *(__half2*)(&g_UhT[off + j]) = __halves2half2(
                    __float2half_rn(acc[i][j] * 0.125f),
                    __float2half_rn(acc[i][j + 1] * 0.125f));
            }
        }
        __syncthreads();
    }
}

// ---------------------------------------------------------------------------
// Kernel: mask correction using precomputed flags (fast path: 1 LDG + exit).
// Slow path identical to R14 (generic correctness; unused for all-ones mask).
// ---------------------------------------------------------------------------
__global__ __launch_bounds__(256) void mask_fix2(const float* __restrict__ x,
                                                 const float* __restrict__ wq,
                                                 const float* __restrict__ wk,
                                                 const float* __restrict__ wv,
                                                 const int* __restrict__ mask,
                                                 float* __restrict__ out)
{
    int bq = blockIdx.x;
    if (g_flags[bq] == 0) return;

    int b = bq >> 11;
    const int* mrow = mask + (size_t)bq * S_;

    __shared__ float xq[1024], qv[1024], xkb[1024], kv[1024], vvv[1024], sc[16];
    const float* xrow = x + (size_t)bq * D_;
    for (int i = threadIdx.x; i < 1024; i += 256) xq[i] = xrow[i];
    __syncthreads();
    for (int i = threadIdx.x; i < 1024; i += 256) {
        float a = 0.f;
        const float* wr = wq + (size_t)i * D_;
        for (int t = 0; t < 1024; t++) a += xq[t] * wr[t];
        qv[i] = a;
    }
    __syncthreads();

    for (int k = 0; k < S_; k++) {
        if (mrow[k] != 0) continue;
        const float* xk = x + ((size_t)b * S_ + k) * D_;
        for (int i = threadIdx.x; i < 1024; i += 256) xkb[i] = xk[i];
        __syncthreads();
        for (int i = threadIdx.x; i < 1024; i += 256) {
            float a = 0.f, c = 0.f;
            const float* wrk = wk + (size_t)i * D_;
            const float* wrv = wv + (size_t)i * D_;
            for (int t = 0; t < 1024; t++) {
                float xv = xkb[t];
                a += xv * wrk[t];
                c += xv * wrv[t];
            }
            kv[i] = a; vvv[i] = c;
        }
        __syncthreads();
        if (threadIdx.x < 16) {
            int h = threadIdx.x;
            float s = 0.f;
            for (int r = 0; r < 64; r++) s += qv[h * 64 + r] * kv[h * 64 + r];
            sc[h] = s * 0.125f;
        }
        __syncthreads();
        float* orow = out + (size_t)bq * D_;
        for (int i = threadIdx.x; i < 1024; i += 256)
            orow[i] += (-1e9f - sc[i >> 6]) * vvv[i];
        __syncthreads();
    }
}

// ---------------------------------------------------------------------------
// Entry point
// ---------------------------------------------------------------------------
extern "C" void kernel_launch(void* const* d_in, const int* in_sizes, int n_in,
                              void* d_out, int out_size)
{
    const float* x    = (const float*)d_in[0];
    const int*   mask = (const int*)  d_in[1];
    const float* wq   = (const float*)d_in[2];
    const float* wk   = (const float*)d_in[3];
    const float* wv   = (const float*)d_in[4];
    float*       out  = (float*)d_out;

    // DEVICE addresses of __device__ globals (never pass host shadow symbols).
    void *p_xh, *p_wvh, *p_ghh, *p_a, *p_uhT;
    cudaGetSymbolAddress(&p_xh,  g_Xh);
    cudaGetSymbolAddress(&p_wvh, g_Wvh);
    cudaGetSymbolAddress(&p_ghh, g_Ghh);
    cudaGetSymbolAddress(&p_a,   g_A);
    cudaGetSymbolAddress(&p_uhT, g_UhT);

    const __half* d_xh  = (const __half*)p_xh;
    const __half* d_wvh = (const __half*)p_wvh;
    __half*       d_ghh = (__half*)p_ghh;
    float*        d_a   = (float*)p_a;
    __half*       d_uhT = (__half*)p_uhT;

    cudaFuncSetAttribute(gram_sym,
        cudaFuncAttributeMaxDynamicSharedMemorySize, G_SMEM);
    cudaFuncSetAttribute(hgemm_bt<true>,
        cudaFuncAttributeMaxDynamicSharedMemorySize, BT_SMEM);
    cudaFuncSetAttribute(hgemm_bt<false>,
        cudaFuncAttributeMaxDynamicSharedMemorySize, BT_SMEM);
    cudaFuncSetAttribute(t_kernel3,
        cudaFuncAttributeMaxDynamicSharedMemorySize, T_SMEM);
    cudaFuncSetAttribute(u_kernel3,
        cudaFuncAttributeMaxDynamicSharedMemorySize, U_SMEM);

    // 0) fused prep: X fp16 (+transpose), Wv fp16, mask row-flag scan
    prep_all<<<dim3(16, 32, 21), 256>>>(x, wv, mask);

    // 1) Symmetric Gram: Ghh_b = fp16(Xh_b^T @ Xh_b), 144 CTAs = 1 wave
    gram_sym<<<dim3(36, 1, 4), 256, G_SMEM>>>();

    // 2) A_b = Ghh_b @ Wvh^T   (M=1024, N=1024, K=1024), BK=64
    hgemm_bt<false><<<dim3(4, 8, 4), 256, BT_SMEM>>>(
        d_ghh, d_wvh, d_a, (__half*)nullptr,
        1024, 1024, 1024, 1024,
        DD_, 0, DD_);

    // 3) T partials + U^T, cp.async-pipelined
    t_kernel3<<<dim3(B_ * H_, 4), 256, T_SMEM>>>(wk);
    u_kernel3<<<dim3(B_ * H_, 4), 256, U_SMEM>>>(wq);

    // 4) out_b = Xh_b @ Uh_b   (M=2048, N=1024, K=1024), BK=64, writes d_out
    hgemm_bt<false><<<dim3(4, 16, 4), 256, BT_SMEM>>>(
        d_xh, d_uhT, out, (__half*)nullptr,
        1024, 1024, 1024, 1024,
        (size_t)2048 * D_, DD_, (size_t)2048 * D_);

    // 5) mask handling (flag fast path; generic slow path preserved)
    mask_fix2<<<B_ * S_, 256>>>(x, wq, wk, wv, mask, out);
}

// round 16
// speedup vs baseline: 1.0179x; 1.0179x over previous
#include <cuda_runtime.h>
#include <cuda_fp16.h>
#include <cstdint>

// Problem constants (fixed by dataset: B=4, S=2048, D=1024, H=16)
#define B_  4
#define S_  2048
#define D_  1024
#define H_  16
#define DK_ 64
#define M_  (B_ * S_)   // 8192
#define DD_ ((size_t)D_ * D_)

// ---------------------------------------------------------------------------
// Device-global scratch
// ---------------------------------------------------------------------------
__device__ __half g_Xh [(size_t)M_ * D_];          // X fp16   [b*2048+s][d]
__device__ __half g_XhT[(size_t)M_ * D_];          // X^T fp16 [b][d][s]
__device__ __half g_Wvh[DD_];                      // Wv hi
__device__ __half g_Ghh[(size_t)B_ * DD_];         // Gram hi  [b][i][j]
__device__ float  g_A  [(size_t)B_ * DD_];         // A = G @ Wv^T  [b][j][n]
__device__ float  g_Tp [(size_t)B_ * H_ * 4 * DK_ * DK_];  // T split-K partials
__device__ __half g_UhT[(size_t)B_ * DD_];         // U^T hi   [b][n][j]

// Lower-triangle block enumeration for the symmetric Gram (8x8 blocks of 128)
__device__ __constant__ int GBI[36] =
    {0,1,1,2,2,2,3,3,3,3,4,4,4,4,4,5,5,5,5,5,5,
     6,6,6,6,6,6,6,7,7,7,7,7,7,7,7};
__device__ __constant__ int GBJ[36] =
    {0,0,1,0,1,2,0,1,2,3,0,1,2,3,4,0,1,2,3,4,5,
     0,1,2,3,4,5,6,0,1,2,3,4,5,6,7};

// ---------------------------------------------------------------------------
// Helpers
// ---------------------------------------------------------------------------
__device__ __forceinline__ uint32_t smem_u32(const void* p) {
    uint32_t a;
    asm("{ .reg .u64 t; cvta.to.shared.u64 t, %1; cvt.u32.u64 %0, t; }"
        : "=r"(a) : "l"(p));
    return a;
}
__device__ __forceinline__ void cp16(uint32_t saddr, const void* gptr) {
    asm volatile("cp.async.ca.shared.global [%0], [%1], 16;"
                 :: "r"(saddr), "l"(gptr) : "memory");
}
__device__ __forceinline__ void cp_commit() {
    asm volatile("cp.async.commit_group;" ::: "memory");
}
template <int N>
__device__ __forceinline__ void cp_wait() {
    asm volatile("cp.async.wait_group %0;" :: "n"(N) : "memory");
}
__device__ __forceinline__ void ldsm4(uint32_t* r, uint32_t addr) {
    asm volatile("ldmatrix.sync.aligned.m8n8.x4.shared.b16 {%0,%1,%2,%3}, [%4];"
                 : "=r"(r[0]), "=r"(r[1]), "=r"(r[2]), "=r"(r[3]) : "r"(addr));
}
__device__ __forceinline__ void mma16816(float* d, const uint32_t* a,
                                         uint32_t b0, uint32_t b1) {
    asm volatile(
        "mma.sync.aligned.m16n8k16.row.col.f32.f16.f16.f32 "
        "{%0,%1,%2,%3}, {%4,%5,%6,%7}, {%8,%9}, {%0,%1,%2,%3};"
        : "+f"(d[0]), "+f"(d[1]), "+f"(d[2]), "+f"(d[3])
        : "r"(a[0]), "r"(a[1]), "r"(a[2]), "r"(a[3]), "r"(b0), "r"(b1));
}

// ---------------------------------------------------------------------------
// Kernel: x fp32 -> g_Xh (fp16) + g_XhT (fp16 transposed), one pass
// ---------------------------------------------------------------------------
__global__ __launch_bounds__(256) void x_prep(const float* __restrict__ x)
{
    int d0 = blockIdx.x * 64, s0 = blockIdx.y * 64, b = blockIdx.z;
    __shared__ __half t[64][72];
    int tid = threadIdx.x;
    int rr = tid >> 4;
    int cc = (tid & 15) * 4;
#pragma unroll
    for (int pass = 0; pass < 4; pass++) {
        int r = rr + pass * 16;
        size_t go = ((size_t)b * 2048 + s0 + r) * D_ + d0 + cc;
        float4 v = *(const float4*)(x + go);
        __half h0 = __float2half_rn(v.x), h1 = __float2half_rn(v.y);
        __half h2 = __float2half_rn(v.z), h3 = __float2half_rn(v.w);
        __half2 p0 = __halves2half2(h0, h1), p1 = __halves2half2(h2, h3);
        uint2 pk;
        pk.x = *(uint32_t*)&p0; pk.y = *(uint32_t*)&p1;
        *(uint2*)(&g_Xh[go]) = pk;
        t[cc + 0][r] = h0; t[cc + 1][r] = h1;
        t[cc + 2][r] = h2; t[cc + 3][r] = h3;
    }
    __syncthreads();
#pragma unroll
    for (int pass = 0; pass < 4; pass++) {
        int dr = rr + pass * 16;
        __half2 q0 = __halves2half2(t[dr][cc + 0], t[dr][cc + 1]);
        __half2 q1 = __halves2half2(t[dr][cc + 2], t[dr][cc + 3]);
        uint2 pk;
        pk.x = *(uint32_t*)&q0; pk.y = *(uint32_t*)&q1;
        *(uint2*)(&g_XhT[(size_t)b * D_ * 2048 + (size_t)(d0 + dr) * 2048 + s0 + cc]) = pk;
    }
}

// ---------------------------------------------------------------------------
// Kernel: Wv fp32 -> fp16 hi only
// ---------------------------------------------------------------------------
__global__ __launch_bounds__(256) void f16_wv(const float* __restrict__ src, int n4)
{
    int i = blockIdx.x * 256 + threadIdx.x;
    if (i >= n4) return;
    float4 v = ((const float4*)src)[i];
    __half2* hp = (__half2*)g_Wvh + (size_t)i * 2;
    hp[0] = __halves2half2(__float2half_rn(v.x), __float2half_rn(v.y));
    hp[1] = __halves2half2(__float2half_rn(v.z), __float2half_rn(v.w));
}

// ---------------------------------------------------------------------------
// Symmetric Gram kernel: Ghh_b = fp16(XhT_b @ XhT_b^T), lower-triangle tiles.
// 128x128 tile, BK=64, K=2048, 8 warps (2m x 4n, 64x32 each), 3-stage cp.async.
// grid = (36, 1, 4) = 144 CTAs (one full wave).
// ---------------------------------------------------------------------------
#define GPAD    144
#define G_AB    (128 * GPAD)          // 18432
#define G_STAGE (2 * G_AB)            // 36864
#define G_SMEM  (3 * G_STAGE)         // 110592

__global__ __launch_bounds__(256, 1) void gram_sym()
{
    extern __shared__ char dsm[];
    const uint32_t sbase = smem_u32(dsm);

    const int tid  = threadIdx.x;
    const int lane = tid & 31;
    const int wid  = tid >> 5;
    const int wm   = wid & 1;
    const int wn   = wid >> 1;
    const int b    = blockIdx.z;
    const int bi   = GBI[blockIdx.x];
    const int bj   = GBJ[blockIdx.x];

    const __half* A0 = g_XhT + (size_t)b * D_ * 2048 + (size_t)bi * 128 * 2048;
    const __half* B0 = g_XhT + (size_t)b * D_ * 2048 + (size_t)bj * 128 * 2048;

    auto load_chunk = [&](int buf, int k0) {
        uint32_t st = sbase + buf * G_STAGE;
#pragma unroll
        for (int it = 0; it < 4; it++) {
            int sidx = tid + it * 256;
            int r = sidx >> 3, s = sidx & 7;
            cp16(st + r * GPAD + s * 16,        A0 + (size_t)r * 2048 + k0 + s * 8);
            cp16(st + G_AB + r * GPAD + s * 16, B0 + (size_t)r * 2048 + k0 + s * 8);
        }
    };

    float acc[4][4][4];
#pragma unroll
    for (int mt = 0; mt < 4; mt++)
#pragma unroll
        for (int nt = 0; nt < 4; nt++)
#pragma unroll
            for (int e = 0; e < 4; e++) acc[mt][nt][e] = 0.f;

    load_chunk(0, 0);   cp_commit();
    load_chunk(1, 64);  cp_commit();

    const int arow  = lane & 15;
    const int aksel = lane >> 4;
    const int brow  = (lane & 7) + 8 * ((lane >> 3) & 1);
    const int bksel = lane >> 4;
    const int NC = 2048 >> 6;

    for (int c = 0; c < NC; c++) {
        const int buf = c % 3;
        cp_wait<1>();
        __syncthreads();
        if (c + 2 < NC) load_chunk((c + 2) % 3, (c + 2) * 64);
        cp_commit();

        const uint32_t st = sbase + buf * G_STAGE;
#pragma unroll
        for (int ks = 0; ks < 4; ks++) {
            const int k0 = ks * 16;
            uint32_t af[4][4], bf[2][4];
#pragma unroll
            for (int mt = 0; mt < 4; mt++) {
                uint32_t ad = st + (wm * 64 + mt * 16 + arow) * GPAD
                            + (k0 + aksel * 8) * 2;
                ldsm4(af[mt], ad);
            }
#pragma unroll
            for (int ng = 0; ng < 2; ng++) {
                uint32_t bd = st + G_AB
                            + (wn * 32 + ng * 16 + brow) * GPAD
                            + (k0 + bksel * 8) * 2;
                ldsm4(bf[ng], bd);
            }
#pragma unroll
            for (int mt = 0; mt < 4; mt++)
#pragma unroll
                for (int nt = 0; nt < 4; nt++) {
                    const int ng = nt >> 1, w = nt & 1;
                    mma16816(acc[mt][nt], af[mt], bf[ng][w], bf[ng][w + 2]);
                }
        }
    }

    // Stage fp16 tile in smem (row stride 136 halves = 272B)
    __syncthreads();
    __half* tile = (__half*)dsm;
#pragma unroll
    for (int mt = 0; mt < 4; mt++)
#pragma unroll
        for (int nt = 0; nt < 4; nt++)
#pragma unroll
            for (int hr = 0; hr < 2; hr++) {
                int r = wm * 64 + mt * 16 + (lane >> 2) + hr * 8;
                int col = wn * 32 + nt * 8 + (lane & 3) * 2;
                *(__half2*)&tile[r * 136 + col] = __halves2half2(
                    __float2half_rn(acc[mt][nt][hr * 2 + 0]),
                    __float2half_rn(acc[mt][nt][hr * 2 + 1]));
            }
    __syncthreads();

    __half* Gb = g_Ghh + (size_t)b * DD_;
    for (int e = tid; e < 128 * 16; e += 256) {
        int r = e >> 4, q = e & 15;
        *(uint4*)(Gb + (size_t)(bi * 128 + r) * 1024 + bj * 128 + q * 8) =
            *(uint4*)&tile[r * 136 + q * 8];
    }
    if (bi != bj) {
        int j = tid >> 1, base_i = (tid & 1) * 64;
#pragma unroll
        for (int ii = 0; ii < 32; ii++) {
            int i = base_i + ii * 2;
            __half2 v = __halves2half2(tile[i * 136 + j], tile[(i + 1) * 136 + j]);
            *(__half2*)(Gb + (size_t)(bj * 128 + j) * 1024 + bi * 128 + i) = v;
        }
    }
}

// ---------------------------------------------------------------------------
// Big-tile single-term HMMA GEMM: C = A0 @ B0^T, fp16 in, fp32/fp16 out.
// BM=128 BN=256 BK=64, 3-stage cp.async, 256 threads, 8 warps 2m x 4n (64x64).
// ---------------------------------------------------------------------------
#define BTPAD      144
#define BT_A_BYTES (128 * BTPAD)
#define BT_B_BYTES (256 * BTPAD)
#define BT_STAGE   (BT_A_BYTES + BT_B_BYTES)
#define BT_SMEM    (3 * BT_STAGE)           // 165888

template <bool HALFC>
__global__ __launch_bounds__(256, 1) void hgemm_bt(
    const __half* __restrict__ A0p, const __half* __restrict__ B0p,
    float* __restrict__ Cp, __half* __restrict__ ChP,
    int K, int lda, int ldb, int ldc,
    size_t aZ, size_t bZ, size_t cZ)
{
    extern __shared__ char dsm[];
    const uint32_t sbase = smem_u32(dsm);

    const int tid  = threadIdx.x;
    const int lane = tid & 31;
    const int wid  = tid >> 5;
    const int wm   = wid & 1;
    const int wn   = wid >> 1;
    const int z    = blockIdx.z;
    const int m0   = blockIdx.y * 128;
    const int n0   = blockIdx.x * 256;

    const __half* A0 = A0p + z * aZ + (size_t)m0 * lda;
    const __half* B0 = B0p + z * bZ + (size_t)n0 * ldb;

    auto load_chunk = [&](int buf, int k0) {
        uint32_t st = sbase + buf * BT_STAGE;
#pragma unroll
        for (int it = 0; it < 4; it++) {
            int sidx = tid + it * 256;
            int r = sidx >> 3, s = sidx & 7;
            cp16(st + r * BTPAD + s * 16, A0 + (size_t)r * lda + k0 + s * 8);
        }
#pragma unroll
        for (int it = 0; it < 8; it++) {
            int sidx = tid + it * 256;
            int r = sidx >> 3, s = sidx & 7;
            cp16(st + BT_A_BYTES + r * BTPAD + s * 16,
                 B0 + (size_t)r * ldb + k0 + s * 8);
        }
    };

    float acc[4][8][4];
#pragma unroll
    for (int mt = 0; mt < 4; mt++)
#pragma unroll
        for (int nt = 0; nt < 8; nt++)
#pragma unroll
            for (int e = 0; e < 4; e++) acc[mt][nt][e] = 0.f;

    load_chunk(0, 0);   cp_commit();
    load_chunk(1, 64);  cp_commit();

    const int arow  = lane & 15;
    const int aksel = lane >> 4;
    const int brow  = (lane & 7) + 8 * ((lane >> 3) & 1);
    const int bksel = lane >> 4;
    const int NC = K >> 6;

    for (int c = 0; c < NC; c++) {
        const int buf = c % 3;
        cp_wait<1>();
        __syncthreads();
        if (c + 2 < NC) load_chunk((c + 2) % 3, (c + 2) * 64);
        cp_commit();

        const uint32_t st = sbase + buf * BT_STAGE;
#pragma unroll
        for (int ks = 0; ks < 4; ks++) {
            const int k0 = ks * 16;
            uint32_t af[4][4], bf[4][4];
#pragma unroll
            for (int mt = 0; mt < 4; mt++) {
                uint32_t ad = st + (wm * 64 + mt * 16 + arow) * BTPAD
                            + (k0 + aksel * 8) * 2;
                ldsm4(af[mt], ad);
            }
#pragma unroll
            for (int ng = 0; ng < 4; ng++) {
                uint32_t bd = st + BT_A_BYTES
                            + (wn * 64 + ng * 16 + brow) * BTPAD
                            + (k0 + bksel * 8) * 2;
                ldsm4(bf[ng], bd);
            }
#pragma unroll
            for (int mt = 0; mt < 4; mt++)
#pragma unroll
                for (int nt = 0; nt < 8; nt++) {
                    const int ng = nt >> 1, w = nt & 1;
                    mma16816(acc[mt][nt], af[mt], bf[ng][w], bf[ng][w + 2]);
                }
        }
    }

    if (HALFC) {
        __half* Ch = ChP + z * cZ;
#pragma unroll
        for (int mt = 0; mt < 4; mt++) {
            const int rbase = m0 + wm * 64 + mt * 16 + (lane >> 2);
#pragma unroll
            for (int nt = 0; nt < 8; nt++) {
                const int col = n0 + wn * 64 + nt * 8 + (lane & 3) * 2;
#pragma unroll
                for (int hr = 0; hr < 2; hr++) {
                    size_t off = (size_t)(rbase + hr * 8) * ldc + col;
                    *(__half2*)(Ch + off) = __halves2half2(
                        __float2half_rn(acc[mt][nt][hr * 2 + 0]),
                        __float2half_rn(acc[mt][nt][hr * 2 + 1]));
                }
            }
        }
    } else {
        float* C = Cp + z * cZ;
#pragma unroll
        for (int mt = 0; mt < 4; mt++) {
            const int rbase = m0 + wm * 64 + mt * 16 + (lane >> 2);
#pragma unroll
            for (int nt = 0; nt < 8; nt++) {
                const int col = n0 + wn * 64 + nt * 8 + (lane & 3) * 2;
                *(float2*)(C + (size_t)rbase * ldc + col) =
                    make_float2(acc[mt][nt][0], acc[mt][nt][1]);
                *(float2*)(C + (size_t)(rbase + 8) * ldc + col) =
                    make_float2(acc[mt][nt][2], acc[mt][nt][3]);
            }
        }
    }
}

// ---------------------------------------------------------------------------
// Kernel: split-K partials of T_bh = Wk_h @ A_b[:, h*64:+64]
// cp.async double-buffered; inner loop float4-vectorized (j in groups of 4,
// accumulation still strictly j-ascending per output -> bit-identical).
// ---------------------------------------------------------------------------
#define TPADF   68
#define T_MAT   (64 * TPADF * 4)        // 17408 B per matrix
#define T_STAGE (2 * T_MAT)
#define T_SMEM  (2 * T_STAGE)           // 69632 B

__global__ __launch_bounds__(256) void t_kernel3(const float* __restrict__ wk)
{
    extern __shared__ char dsm[];
    const uint32_t sbase = smem_u32(dsm);
    int bh = blockIdx.x, sp = blockIdx.y;
    int b = bh >> 4, h = bh & 15;
    int tid = threadIdx.x, ti = tid >> 4, tj = tid & 15;

    const float* wkh = wk + (size_t)(h * 64) * D_;
    const float* Ab  = g_A + (size_t)b * DD_ + h * 64;

    auto load_tiles = [&](int stage, int j0) {
        uint32_t st = sbase + stage * T_STAGE;
#pragma unroll
        for (int it = 0; it < 4; it++) {
            int sidx = tid + it * 256;
            int r = sidx >> 4, s = sidx & 15;
            cp16(st + r * (TPADF * 4) + s * 16,
                 wkh + (size_t)r * D_ + j0 + s * 4);
            cp16(st + T_MAT + r * (TPADF * 4) + s * 16,
                 Ab + (size_t)(j0 + r) * D_ + s * 4);
        }
    };

    float acc[4][4] = {};
    load_tiles(0, sp * 256);
    cp_commit();

    for (int it = 0; it < 4; it++) {
        cp_wait<0>();
        __syncthreads();
        if (it + 1 < 4) load_tiles((it + 1) & 1, sp * 256 + (it + 1) * 64);
        cp_commit();

        const float* K_s = (const float*)(dsm + (it & 1) * T_STAGE);
        const float* A_s = (const float*)(dsm + (it & 1) * T_STAGE + T_MAT);
#pragma unroll 4
        for (int j4 = 0; j4 < 64; j4 += 4) {
            float4 kr4[4], ar4[4];
#pragma unroll
            for (int i = 0; i < 4; i++)
                kr4[i] = *(const float4*)&K_s[(ti * 4 + i) * TPADF + j4];
#pragma unroll
            for (int jj = 0; jj < 4; jj++)
                ar4[jj] = *(const float4*)&A_s[(j4 + jj) * TPADF + tj * 4];
#pragma unroll
            for (int jj = 0; jj < 4; jj++) {
                float kj[4] = {
                    jj == 0 ? kr4[0].x : jj == 1 ? kr4[0].y : jj == 2 ? kr4[0].z : kr4[0].w,
                    jj == 0 ? kr4[1].x : jj == 1 ? kr4[1].y : jj == 2 ? kr4[1].z : kr4[1].w,
                    jj == 0 ? kr4[2].x : jj == 1 ? kr4[2].y : jj == 2 ? kr4[2].z : kr4[2].w,
                    jj == 0 ? kr4[3].x : jj == 1 ? kr4[3].y : jj == 2 ? kr4[3].z : kr4[3].w };
                float aj[4] = { ar4[jj].x, ar4[jj].y, ar4[jj].z, ar4[jj].w };
#pragma unroll
                for (int i = 0; i < 4; i++)
#pragma unroll
                    for (int c = 0; c < 4; c++)
                        acc[i][c] = fmaf(kj[i], aj[c], acc[i][c]);
            }
        }
        __syncthreads();
    }
#pragma unroll
    for (int i = 0; i < 4; i++)
#pragma unroll
        for (int c = 0; c < 4; c++)
            g_Tp[((size_t)bh * 4 + sp) * 4096 + (ti * 4 + i) * 64 + tj * 4 + c]
                = acc[i][c];
}

// ---------------------------------------------------------------------------
// Kernel: U^T[b][h*64+c][j] = (1/8) sum_r Wq[h*64+r][j] T_bh[r][c] (fp16 hi)
// cp.async double-buffered Wq tiles; float4-vectorized loads (same r order).
// ---------------------------------------------------------------------------
#define U_SMEM  (T_MAT + 2 * T_MAT)     // 52224 B

__global__ __launch_bounds__(256) void u_kernel3(const float* __restrict__ wq)
{
    extern __shared__ char dsm[];
    const uint32_t sbase = smem_u32(dsm);
    int bh = blockIdx.x, slice = blockIdx.y;
    int b = bh >> 4, h = bh & 15;
    int tid = threadIdx.x, ti = tid >> 4, tj = tid & 15;

    float* T_s = (float*)dsm;
    const float* wqh = wq + (size_t)(h * 64) * D_;

    auto load_w = [&](int stage, int j0) {
        uint32_t st = sbase + T_MAT + stage * T_MAT;
#pragma unroll
        for (int it = 0; it < 4; it++) {
            int sidx = tid + it * 256;
            int r = sidx >> 4, s = sidx & 15;
            cp16(st + r * (TPADF * 4) + s * 16,
                 wqh + (size_t)r * D_ + j0 + s * 4);
        }
    };

    load_w(0, slice * 256);
    cp_commit();

    const float* Tp = g_Tp + (size_t)bh * 4 * 4096;
    for (int e = tid; e < 4096; e += 256) {
        float s = Tp[e] + Tp[e + 4096] + Tp[e + 8192] + Tp[e + 12288];
        T_s[(e >> 6) * TPADF + (e & 63)] = s;
    }

    for (int ch = 0; ch < 4; ch++) {
        int j0 = slice * 256 + ch * 64;
        cp_wait<0>();
        __syncthreads();
        if (ch + 1 < 4) load_w((ch + 1) & 1, slice * 256 + (ch + 1) * 64);
        cp_commit();

        const float* W_s = (const float*)(dsm + T_MAT + (ch & 1) * T_MAT);
        float acc[4][4] = {};
#pragma unroll 8
        for (int r = 0; r < 64; r++) {
            float4 tr4 = *(const float4*)&T_s[r * TPADF + ti * 4];
            float4 wr4 = *(const float4*)&W_s[r * TPADF + tj * 4];
            float tr[4] = {tr4.x, tr4.y, tr4.z, tr4.w};
            float wr[4] = {wr4.x, wr4.y, wr4.z, wr4.w};
#pragma unroll
            for (int i = 0; i < 4; i++)
#pragma unroll
                for (int j = 0; j < 4; j++)
                    acc[i][j] = fmaf(tr[i], wr[j], acc[i][j]);
        }
#pragma unroll
        for (int i = 0; i < 4; i++) {
            int c = ti * 4 + i;
            size_t off = (size_t)b * DD_ + (size_t)(h * 64 + c) * D_ + j0 + tj * 4;
#pragma unroll
            for (int j = 0; j < 4; j += 2) {
                *(__half2*)(&g_UhT[off + j]) = __halves2half2(
                    __float2half_rn(acc[i][j] * 0.125f),
                    __float2half_rn(acc[i][j + 1] * 0.125f));
            }
        }
        __syncthreads();
    }
}

// ---------------------------------------------------------------------------
// Kernel: mask correction (int4-vectorized fast scan; generic slow path)
// ---------------------------------------------------------------------------
__global__ __launch_bounds__(256) void mask_fix(const float* __restrict__ x,
                                                const float* __restrict__ wq,
                                                const float* __restrict__ wk,
                                                const float* __restrict__ wv,
                                                const int* __restrict__ mask,
                                                float* __restrict__ out)
{
    int bq = blockIdx.x;
    int b  = bq >> 11;
    const int* mrow = mask + (size_t)bq * S_;

    const int4* m4 = (const int4*)mrow;
    bool zf = false;
#pragma unroll
    for (int it = 0; it < 2; it++) {
        int4 v = m4[threadIdx.x + it * 256];
        zf |= (v.x == 0) | (v.y == 0) | (v.z == 0) | (v.w == 0);
    }
    if (!__syncthreads_or(zf)) return;

    // ---- slow path (generic correctness; not exercised by all-ones mask) ----
    __shared__ float xq[1024], qv[1024], xkb[1024], kv[1024], vvv[1024], sc[16];
    const float* xrow = x + (size_t)bq * D_;
    for (int i = threadIdx.x; i < 1024; i += 256) xq[i] = xrow[i];
    __syncthreads();
    for (int i = threadIdx.x; i < 1024; i += 256) {
        float a = 0.f;
        const float* wr = wq + (size_t)i * D_;
        for (int t = 0; t < 1024; t++) a += xq[t] * wr[t];
        qv[i] = a;
    }
    __syncthreads();

    for (int k = 0; k < S_; k++) {
        if (mrow[k] != 0) continue;
        const float* xk = x + ((size_t)b * S_ + k) * D_;
        for (int i = threadIdx.x; i < 1024; i += 256) xkb[i] = xk[i];
        __syncthreads();
        for (int i = threadIdx.x; i < 1024; i += 256) {
            float a = 0.f, c = 0.f;
            const float* wrk = wk + (size_t)i * D_;
            const float* wrv = wv + (size_t)i * D_;
            for (int t = 0; t < 1024; t++) {
                float xv = xkb[t];
                a += xv * wrk[t];
                c += xv * wrv[t];
            }
            kv[i] = a; vvv[i] = c;
        }
        __syncthreads();
        if (threadIdx.x < 16) {
            int h = threadIdx.x;
            float s = 0.f;
            for (int r = 0; r < 64; r++) s += qv[h * 64 + r] * kv[h * 64 + r];
            sc[h] = s * 0.125f;
        }
        __syncthreads();
        float* orow = out + (size_t)bq * D_;
        for (int i = threadIdx.x; i < 1024; i += 256)
            orow[i] += (-1e9f - sc[i >> 6]) * vvv[i];
        __syncthreads();
    }
}

// ---------------------------------------------------------------------------
// Entry point
// ---------------------------------------------------------------------------
extern "C" void kernel_launch(void* const* d_in, const int* in_sizes, int n_in,
                              void* d_out, int out_size)
{
    const float* x    = (const float*)d_in[0];
    const int*   mask = (const int*)  d_in[1];
    const float* wq   = (const float*)d_in[2];
    const float* wk   = (const float*)d_in[3];
    const float* wv   = (const float*)d_in[4];
    float*       out  = (float*)d_out;

    // DEVICE addresses of __device__ globals (never pass host shadow symbols).
    void *p_xh, *p_wvh, *p_ghh, *p_a, *p_uhT;
    cudaGetSymbolAddress(&p_xh,  g_Xh);
    cudaGetSymbolAddress(&p_wvh, g_Wvh);
    cudaGetSymbolAddress(&p_ghh, g_Ghh);
    cudaGetSymbolAddress(&p_a,   g_A);
    cudaGetSymbolAddress(&p_uhT, g_UhT);

    const __half* d_xh  = (const __half*)p_xh;
    const __half* d_wvh = (const __half*)p_wvh;
    __half*       d_ghh = (__half*)p_ghh;
    float*        d_a   = (float*)p_a;
    __half*       d_uhT = (__half*)p_uhT;

    cudaFuncSetAttribute(gram_sym,
        cudaFuncAttributeMaxDynamicSharedMemorySize, G_SMEM);
    cudaFuncSetAttribute(hgemm_bt<true>,
        cudaFuncAttributeMaxDynamicSharedMemorySize, BT_SMEM);
    cudaFuncSetAttribute(hgemm_bt<false>,
        cudaFuncAttributeMaxDynamicSharedMemorySize, BT_SMEM);
    cudaFuncSetAttribute(t_kernel3,
        cudaFuncAttributeMaxDynamicSharedMemorySize, T_SMEM);
    cudaFuncSetAttribute(u_kernel3,
        cudaFuncAttributeMaxDynamicSharedMemorySize, U_SMEM);

    // 0) conversions (R14 layout)
    x_prep<<<dim3(16, 32, 4), 256>>>(x);
    f16_wv<<<D_ * D_ / 4 / 256, 256>>>(wv, D_ * D_ / 4);

    // 1) Symmetric Gram: Ghh_b = fp16(Xh_b^T @ Xh_b), 144 CTAs = 1 wave
    gram_sym<<<dim3(36, 1, 4), 256, G_SMEM>>>();

    // 2) A_b = Ghh_b @ Wvh^T   (M=1024, N=1024, K=1024), BK=64
    hgemm_bt<false><<<dim3(4, 8, 4), 256, BT_SMEM>>>(
        d_ghh, d_wvh, d_a, (__half*)nullptr,
        1024, 1024, 1024, 1024,
        DD_, 0, DD_);

    // 3) T partials + U^T, cp.async-pipelined, float4 inner loops
    t_kernel3<<<dim3(B_ * H_, 4), 256, T_SMEM>>>(wk);
    u_kernel3<<<dim3(B_ * H_, 4), 256, U_SMEM>>>(wq);

    // 4) out_b = Xh_b @ Uh_b   (M=2048, N=1024, K=1024), BK=64, writes d_out
    hgemm_bt<false><<<dim3(4, 16, 4), 256, BT_SMEM>>>(
        d_xh, d_uhT, out, (__half*)nullptr,
        1024, 1024, 1024, 1024,
        (size_t)2048 * D_, DD_, (size_t)2048 * D_);

    // 5) generic mask handling (R14 version)
    mask_fix<<<B_ * S_, 256>>>(x, wq, wk, wv, mask, out);
}

// round 17
// speedup vs baseline: 1.0327x; 1.0146x over previous
#include <cuda_runtime.h>
#include <cuda_fp16.h>
#include <cstdint>

// Problem constants (fixed by dataset: B=4, S=2048, D=1024, H=16)
#define B_  4
#define S_  2048
#define D_  1024
#define H_  16
#define DK_ 64
#define M_  (B_ * S_)   // 8192
#define DD_ ((size_t)D_ * D_)

// ---------------------------------------------------------------------------
// Device-global scratch
// ---------------------------------------------------------------------------
__device__ __half g_Xh [(size_t)M_ * D_];          // X fp16   [b*2048+s][d]
__device__ __half g_XhT[(size_t)M_ * D_];          // X^T fp16 [b][d][s]
__device__ __half g_Wvh[DD_];                      // Wv hi
__device__ __half g_Ghh[(size_t)B_ * DD_];         // Gram hi  [b][i][j]
__device__ __half g_Ah [(size_t)B_ * DD_];         // A = G @ Wv^T (fp16) [b][j][n]
__device__ float  g_Tp [(size_t)B_ * H_ * 4 * DK_ * DK_];  // T split-K partials
__device__ __half g_UhT[(size_t)B_ * DD_];         // U^T hi   [b][n][j]

// Lower-triangle block enumeration for the symmetric Gram (8x8 blocks of 128)
__device__ __constant__ int GBI[36] =
    {0,1,1,2,2,2,3,3,3,3,4,4,4,4,4,5,5,5,5,5,5,
     6,6,6,6,6,6,6,7,7,7,7,7,7,7,7};
__device__ __constant__ int GBJ[36] =
    {0,0,1,0,1,2,0,1,2,3,0,1,2,3,4,0,1,2,3,4,5,
     0,1,2,3,4,5,6,0,1,2,3,4,5,6,7};

// ---------------------------------------------------------------------------
// Helpers
// ---------------------------------------------------------------------------
__device__ __forceinline__ uint32_t smem_u32(const void* p) {
    uint32_t a;
    asm("{ .reg .u64 t; cvta.to.shared.u64 t, %1; cvt.u32.u64 %0, t; }"
        : "=r"(a) : "l"(p));
    return a;
}
__device__ __forceinline__ void cp16(uint32_t saddr, const void* gptr) {
    asm volatile("cp.async.ca.shared.global [%0], [%1], 16;"
                 :: "r"(saddr), "l"(gptr) : "memory");
}
__device__ __forceinline__ void cp_commit() {
    asm volatile("cp.async.commit_group;" ::: "memory");
}
template <int N>
__device__ __forceinline__ void cp_wait() {
    asm volatile("cp.async.wait_group %0;" :: "n"(N) : "memory");
}
__device__ __forceinline__ void ldsm4(uint32_t* r, uint32_t addr) {
    asm volatile("ldmatrix.sync.aligned.m8n8.x4.shared.b16 {%0,%1,%2,%3}, [%4];"
                 : "=r"(r[0]), "=r"(r[1]), "=r"(r[2]), "=r"(r[3]) : "r"(addr));
}
__device__ __forceinline__ void mma16816(float* d, const uint32_t* a,
                                         uint32_t b0, uint32_t b1) {
    asm volatile(
        "mma.sync.aligned.m16n8k16.row.col.f32.f16.f16.f32 "
        "{%0,%1,%2,%3}, {%4,%5,%6,%7}, {%8,%9}, {%0,%1,%2,%3};"
        : "+f"(d[0]), "+f"(d[1]), "+f"(d[2]), "+f"(d[3])
        : "r"(a[0]), "r"(a[1]), "r"(a[2]), "r"(a[3]), "r"(b0), "r"(b1));
}

// ---------------------------------------------------------------------------
// Fused prep kernel. grid (16, 32, 5), 256 threads.
//  z 0..3 : x fp32 -> g_Xh + g_XhT (64x64 tile per block, batch = z)
//  z == 4 : Wv fp32 -> fp16 hi (512 blocks x 512 float4 each)
// (Mirror/mask kept at their proven R14 forms elsewhere.)
// ---------------------------------------------------------------------------
__global__ __launch_bounds__(256) void prep_all(const float* __restrict__ x,
                                                const float* __restrict__ wv)
{
    __shared__ __half t[64][72];
    int tid = threadIdx.x;
    int z = blockIdx.z;

    if (z < 4) {
        int d0 = blockIdx.x * 64, s0 = blockIdx.y * 64, b = z;
        int rr = tid >> 4;
        int cc = (tid & 15) * 4;
#pragma unroll
        for (int pass = 0; pass < 4; pass++) {
            int r = rr + pass * 16;
            size_t go = ((size_t)b * 2048 + s0 + r) * D_ + d0 + cc;
            float4 v = *(const float4*)(x + go);
            __half h0 = __float2half_rn(v.x), h1 = __float2half_rn(v.y);
            __half h2 = __float2half_rn(v.z), h3 = __float2half_rn(v.w);
            __half2 p0 = __halves2half2(h0, h1), p1 = __halves2half2(h2, h3);
            uint2 pk;
            pk.x = *(uint32_t*)&p0; pk.y = *(uint32_t*)&p1;
            *(uint2*)(&g_Xh[go]) = pk;
            t[cc + 0][r] = h0; t[cc + 1][r] = h1;
            t[cc + 2][r] = h2; t[cc + 3][r] = h3;
        }
        __syncthreads();
#pragma unroll
        for (int pass = 0; pass < 4; pass++) {
            int dr = rr + pass * 16;
            __half2 q0 = __halves2half2(t[dr][cc + 0], t[dr][cc + 1]);
            __half2 q1 = __halves2half2(t[dr][cc + 2], t[dr][cc + 3]);
            uint2 pk;
            pk.x = *(uint32_t*)&q0; pk.y = *(uint32_t*)&q1;
            *(uint2*)(&g_XhT[(size_t)b * D_ * 2048 +
                             (size_t)(d0 + dr) * 2048 + s0 + cc]) = pk;
        }
    } else {
        int blk = blockIdx.y * 16 + blockIdx.x;        // 0..511
#pragma unroll
        for (int u = 0; u < 2; u++) {
            int i = blk * 512 + tid * 2 + u;           // float4 index < 262144
            float4 v = ((const float4*)wv)[i];
            __half2* hp = (__half2*)g_Wvh + (size_t)i * 2;
            hp[0] = __halves2half2(__float2half_rn(v.x), __float2half_rn(v.y));
            hp[1] = __halves2half2(__float2half_rn(v.z), __float2half_rn(v.w));
        }
    }
}

// ---------------------------------------------------------------------------
// Symmetric Gram kernel: Ghh_b = fp16(XhT_b @ XhT_b^T), lower-triangle tiles.
// 128x128 tile, BK=64, K=2048, 8 warps (2m x 4n, 64x32 each), 3-stage cp.async.
// grid = (36, 1, 4) = 144 CTAs (one full wave). R14-proven mirror writes.
// ---------------------------------------------------------------------------
#define GPAD    144
#define G_AB    (128 * GPAD)          // 18432
#define G_STAGE (2 * G_AB)            // 36864
#define G_SMEM  (3 * G_STAGE)         // 110592

__global__ __launch_bounds__(256, 1) void gram_sym()
{
    extern __shared__ char dsm[];
    const uint32_t sbase = smem_u32(dsm);

    const int tid  = threadIdx.x;
    const int lane = tid & 31;
    const int wid  = tid >> 5;
    const int wm   = wid & 1;
    const int wn   = wid >> 1;
    const int b    = blockIdx.z;
    const int bi   = GBI[blockIdx.x];
    const int bj   = GBJ[blockIdx.x];

    const __half* A0 = g_XhT + (size_t)b * D_ * 2048 + (size_t)bi * 128 * 2048;
    const __half* B0 = g_XhT + (size_t)b * D_ * 2048 + (size_t)bj * 128 * 2048;

    auto load_chunk = [&](int buf, int k0) {
        uint32_t st = sbase + buf * G_STAGE;
#pragma unroll
        for (int it = 0; it < 4; it++) {
            int sidx = tid + it * 256;
            int r = sidx >> 3, s = sidx & 7;
            cp16(st + r * GPAD + s * 16,        A0 + (size_t)r * 2048 + k0 + s * 8);
            cp16(st + G_AB + r * GPAD + s * 16, B0 + (size_t)r * 2048 + k0 + s * 8);
        }
    };

    float acc[4][4][4];
#pragma unroll
    for (int mt = 0; mt < 4; mt++)
#pragma unroll
        for (int nt = 0; nt < 4; nt++)
#pragma unroll
            for (int e = 0; e < 4; e++) acc[mt][nt][e] = 0.f;

    load_chunk(0, 0);   cp_commit();
    load_chunk(1, 64);  cp_commit();

    const int arow  = lane & 15;
    const int aksel = lane >> 4;
    const int brow  = (lane & 7) + 8 * ((lane >> 3) & 1);
    const int bksel = lane >> 4;
    const int NC = 2048 >> 6;

    for (int c = 0; c < NC; c++) {
        const int buf = c % 3;
        cp_wait<1>();
        __syncthreads();
        if (c + 2 < NC) load_chunk((c + 2) % 3, (c + 2) * 64);
        cp_commit();

        const uint32_t st = sbase + buf * G_STAGE;
#pragma unroll
        for (int ks = 0; ks < 4; ks++) {
            const int k0 = ks * 16;
            uint32_t af[4][4], bf[2][4];
#pragma unroll
            for (int mt = 0; mt < 4; mt++) {
                uint32_t ad = st + (wm * 64 + mt * 16 + arow) * GPAD
                            + (k0 + aksel * 8) * 2;
                ldsm4(af[mt], ad);
            }
#pragma unroll
            for (int ng = 0; ng < 2; ng++) {
                uint32_t bd = st + G_AB
                            + (wn * 32 + ng * 16 + brow) * GPAD
                            + (k0 + bksel * 8) * 2;
                ldsm4(bf[ng], bd);
            }
#pragma unroll
            for (int mt = 0; mt < 4; mt++)
#pragma unroll
                for (int nt = 0; nt < 4; nt++) {
                    const int ng = nt >> 1, w = nt & 1;
                    mma16816(acc[mt][nt], af[mt], bf[ng][w], bf[ng][w + 2]);
                }
        }
    }

    // Stage fp16 tile in smem (row stride 136 halves = 272B)
    __syncthreads();
    __half* tile = (__half*)dsm;
#pragma unroll
    for (int mt = 0; mt < 4; mt++)
#pragma unroll
        for (int nt = 0; nt < 4; nt++)
#pragma unroll
            for (int hr = 0; hr < 2; hr++) {
                int r = wm * 64 + mt * 16 + (lane >> 2) + hr * 8;
                int col = wn * 32 + nt * 8 + (lane & 3) * 2;
                *(__half2*)&tile[r * 136 + col] = __halves2half2(
                    __float2half_rn(acc[mt][nt][hr * 2 + 0]),
                    __float2half_rn(acc[mt][nt][hr * 2 + 1]));
            }
    __syncthreads();

    __half* Gb = g_Ghh + (size_t)b * DD_;
    for (int e = tid; e < 128 * 16; e += 256) {
        int r = e >> 4, q = e & 15;
        *(uint4*)(Gb + (size_t)(bi * 128 + r) * 1024 + bj * 128 + q * 8) =
            *(uint4*)&tile[r * 136 + q * 8];
    }
    if (bi != bj) {
        int j = tid >> 1, base_i = (tid & 1) * 64;
#pragma unroll
        for (int ii = 0; ii < 32; ii++) {
            int i = base_i + ii * 2;
            __half2 v = __halves2half2(tile[i * 136 + j], tile[(i + 1) * 136 + j]);
            *(__half2*)(Gb + (size_t)(bj * 128 + j) * 1024 + bi * 128 + i) = v;
        }
    }
}

// ---------------------------------------------------------------------------
// Big-tile single-term HMMA GEMM: C = A0 @ B0^T, fp16 in, fp32/fp16 out.
// BM=128 BN=256 BK=64, 3-stage cp.async, 256 threads, 8 warps 2m x 4n (64x64).
// ---------------------------------------------------------------------------
#define BTPAD      144
#define BT_A_BYTES (128 * BTPAD)
#define BT_B_BYTES (256 * BTPAD)
#define BT_STAGE   (BT_A_BYTES + BT_B_BYTES)
#define BT_SMEM    (3 * BT_STAGE)           // 165888

template <bool HALFC>
__global__ __launch_bounds__(256, 1) void hgemm_bt(
    const __half* __restrict__ A0p, const __half* __restrict__ B0p,
    float* __restrict__ Cp, __half* __restrict__ ChP,
    int K, int lda, int ldb, int ldc,
    size_t aZ, size_t bZ, size_t cZ)
{
    extern __shared__ char dsm[];
    const uint32_t sbase = smem_u32(dsm);

    const int tid  = threadIdx.x;
    const int lane = tid & 31;
    const int wid  = tid >> 5;
    const int wm   = wid & 1;
    const int wn   = wid >> 1;
    const int z    = blockIdx.z;
    const int m0   = blockIdx.y * 128;
    const int n0   = blockIdx.x * 256;

    const __half* A0 = A0p + z * aZ + (size_t)m0 * lda;
    const __half* B0 = B0p + z * bZ + (size_t)n0 * ldb;

    auto load_chunk = [&](int buf, int k0) {
        uint32_t st = sbase + buf * BT_STAGE;
#pragma unroll
        for (int it = 0; it < 4; it++) {
            int sidx = tid + it * 256;
            int r = sidx >> 3, s = sidx & 7;
            cp16(st + r * BTPAD + s * 16, A0 + (size_t)r * lda + k0 + s * 8);
        }
#pragma unroll
        for (int it = 0; it < 8; it++) {
            int sidx = tid + it * 256;
            int r = sidx >> 3, s = sidx & 7;
            cp16(st + BT_A_BYTES + r * BTPAD + s * 16,
                 B0 + (size_t)r * ldb + k0 + s * 8);
        }
    };

    float acc[4][8][4];
#pragma unroll
    for (int mt = 0; mt < 4; mt++)
#pragma unroll
        for (int nt = 0; nt < 8; nt++)
#pragma unroll
            for (int e = 0; e < 4; e++) acc[mt][nt][e] = 0.f;

    load_chunk(0, 0);   cp_commit();
    load_chunk(1, 64);  cp_commit();

    const int arow  = lane & 15;
    const int aksel = lane >> 4;
    const int brow  = (lane & 7) + 8 * ((lane >> 3) & 1);
    const int bksel = lane >> 4;
    const int NC = K >> 6;

    for (int c = 0; c < NC; c++) {
        const int buf = c % 3;
        cp_wait<1>();
        __syncthreads();
        if (c + 2 < NC) load_chunk((c + 2) % 3, (c + 2) * 64);
        cp_commit();

        const uint32_t st = sbase + buf * BT_STAGE;
#pragma unroll
        for (int ks = 0; ks < 4; ks++) {
            const int k0 = ks * 16;
            uint32_t af[4][4], bf[4][4];
#pragma unroll
            for (int mt = 0; mt < 4; mt++) {
                uint32_t ad = st + (wm * 64 + mt * 16 + arow) * BTPAD
                            + (k0 + aksel * 8) * 2;
                ldsm4(af[mt], ad);
            }
#pragma unroll
            for (int ng = 0; ng < 4; ng++) {
                uint32_t bd = st + BT_A_BYTES
                            + (wn * 64 + ng * 16 + brow) * BTPAD
                            + (k0 + bksel * 8) * 2;
                ldsm4(bf[ng], bd);
            }
#pragma unroll
            for (int mt = 0; mt < 4; mt++)
#pragma unroll
                for (int nt = 0; nt < 8; nt++) {
                    const int ng = nt >> 1, w = nt & 1;
                    mma16816(acc[mt][nt], af[mt], bf[ng][w], bf[ng][w + 2]);
                }
        }
    }

    if (HALFC) {
        __half* Ch = ChP + z * cZ;
#pragma unroll
        for (int mt = 0; mt < 4; mt++) {
            const int rbase = m0 + wm * 64 + mt * 16 + (lane >> 2);
#pragma unroll
            for (int nt = 0; nt < 8; nt++) {
                const int col = n0 + wn * 64 + nt * 8 + (lane & 3) * 2;
#pragma unroll
                for (int hr = 0; hr < 2; hr++) {
                    size_t off = (size_t)(rbase + hr * 8) * ldc + col;
                    *(__half2*)(Ch + off) = __halves2half2(
                        __float2half_rn(acc[mt][nt][hr * 2 + 0]),
                        __float2half_rn(acc[mt][nt][hr * 2 + 1]));
                }
            }
        }
    } else {
        float* C = Cp + z * cZ;
#pragma unroll
        for (int mt = 0; mt < 4; mt++) {
            const int rbase = m0 + wm * 64 + mt * 16 + (lane >> 2);
#pragma unroll
            for (int nt = 0; nt < 8; nt++) {
                const int col = n0 + wn * 64 + nt * 8 + (lane & 3) * 2;
                *(float2*)(C + (size_t)rbase * ldc + col) =
                    make_float2(acc[mt][nt][0], acc[mt][nt][1]);
                *(float2*)(C + (size_t)(rbase + 8) * ldc + col) =
                    make_float2(acc[mt][nt][2], acc[mt][nt][3]);
            }
        }
    }
}

// ---------------------------------------------------------------------------
// Kernel: split-K partials of T_bh = Wk_h @ A_b[:, h*64:+64]
// cp.async double-buffered; Wk fp32, A fp16 (converted in-loop).
// Accumulation strictly j-ascending per output (deterministic).
// ---------------------------------------------------------------------------
#define TPADF    68
#define T_MAT_K  (64 * TPADF * 4)       // 17408 B (Wk fp32)
#define TPADH    72
#define T_MAT_A  (64 * TPADH * 2)       // 9216 B  (A fp16)
#define T_STAGE  (T_MAT_K + T_MAT_A)    // 26624
#define T_SMEM   (2 * T_STAGE)          // 53248

__global__ __launch_bounds__(256) void t_kernel3(const float* __restrict__ wk)
{
    extern __shared__ char dsm[];
    const uint32_t sbase = smem_u32(dsm);
    int bh = blockIdx.x, sp = blockIdx.y;
    int b = bh >> 4, h = bh & 15;
    int tid = threadIdx.x, ti = tid >> 4, tj = tid & 15;

    const float*  wkh = wk + (size_t)(h * 64) * D_;
    const __half* Ab  = g_Ah + (size_t)b * DD_ + h * 64;

    auto load_tiles = [&](int stage, int j0) {
        uint32_t st = sbase + stage * T_STAGE;
#pragma unroll
        for (int it = 0; it < 4; it++) {           // Wk: 1024 segs, 4/thread
            int sidx = tid + it * 256;
            int r = sidx >> 4, s = sidx & 15;
            cp16(st + r * (TPADF * 4) + s * 16,
                 wkh + (size_t)r * D_ + j0 + s * 4);
        }
#pragma unroll
        for (int it = 0; it < 2; it++) {           // A: 512 segs, 2/thread
            int sidx = tid + it * 256;
            int r = sidx >> 3, s = sidx & 7;
            cp16(st + T_MAT_K + r * (TPADH * 2) + s * 16,
                 Ab + (size_t)(j0 + r) * D_ + s * 8);
        }
    };

    float acc[4][4] = {};
    load_tiles(0, sp * 256);
    cp_commit();

    for (int it = 0; it < 4; it++) {
        cp_wait<0>();
        __syncthreads();
        if (it + 1 < 4) load_tiles((it + 1) & 1, sp * 256 + (it + 1) * 64);
        cp_commit();

        const float*  K_s = (const float*)(dsm + (it & 1) * T_STAGE);
        const __half* A_s = (const __half*)(dsm + (it & 1) * T_STAGE + T_MAT_K);
#pragma unroll 4
        for (int j4 = 0; j4 < 64; j4 += 4) {
            float4 kr4[4];
#pragma unroll
            for (int i = 0; i < 4; i++)
                kr4[i] = *(const float4*)&K_s[(ti * 4 + i) * TPADF + j4];
#pragma unroll
            for (int jj = 0; jj < 4; jj++) {
                __half2 ha = *(const __half2*)&A_s[(j4 + jj) * TPADH + tj * 4];
                __half2 hb = *(const __half2*)&A_s[(j4 + jj) * TPADH + tj * 4 + 2];
                float2 fa = __half22float2(ha), fb = __half22float2(hb);
                float aj[4] = { fa.x, fa.y, fb.x, fb.y };
                float kj[4] = {
                    jj == 0 ? kr4[0].x : jj == 1 ? kr4[0].y : jj == 2 ? kr4[0].z : kr4[0].w,
                    jj == 0 ? kr4[1].x : jj == 1 ? kr4[1].y : jj == 2 ? kr4[1].z : kr4[1].w,
                    jj == 0 ? kr4[2].x : jj == 1 ? kr4[2].y : jj == 2 ? kr4[2].z : kr4[2].w,
                    jj == 0 ? kr4[3].x : jj == 1 ? kr4[3].y : jj == 2 ? kr4[3].z : kr4[3].w };
#pragma unroll
                for (int i = 0; i < 4; i++)
#pragma unroll
                    for (int c = 0; c < 4; c++)
                        acc[i][c] = fmaf(kj[i], aj[c], acc[i][c]);
            }
        }
        __syncthreads();
    }
#pragma unroll
    for (int i = 0; i < 4; i++)
#pragma unroll
        for (int c = 0; c < 4; c++)
            g_Tp[((size_t)bh * 4 + sp) * 4096 + (ti * 4 + i) * 64 + tj * 4 + c]
                = acc[i][c];
}

// ---------------------------------------------------------------------------
// Kernel: U^T[b][h*64+c][j] = (1/8) sum_r Wq[h*64+r][j] T_bh[r][c] (fp16 hi)
// cp.async double-buffered Wq tiles; float4-vectorized (R16-proven).
// ---------------------------------------------------------------------------
#define U_MAT   (64 * TPADF * 4)        // 17408 B
#define U_SMEM  (U_MAT + 2 * U_MAT)     // 52224 B

__global__ __launch_bounds__(256) void u_kernel3(const float* __restrict__ wq)
{
    extern __shared__ char dsm[];
    const uint32_t sbase = smem_u32(dsm);
    int bh = blockIdx.x, slice = blockIdx.y;
    int b = bh >> 4, h = bh & 15;
    int tid = threadIdx.x, ti = tid >> 4, tj = tid & 15;

    float* T_s = (float*)dsm;
    const float* wqh = wq + (size_t)(h * 64) * D_;

    auto load_w = [&](int stage, int j0) {
        uint32_t st = sbase + U_MAT + stage * U_MAT;
#pragma unroll
        for (int it = 0; it < 4; it++) {
            int sidx = tid + it * 256;
            int r = sidx >> 4, s = sidx & 15;
            cp16(st + r * (TPADF * 4) + s * 16,
                 wqh + (size_t)r * D_ + j0 + s * 4);
        }
    };

    load_w(0, slice * 256);
    cp_commit();

    const float* Tp = g_Tp + (size_t)bh * 4 * 4096;
    for (int e = tid; e < 4096; e += 256) {
        float s = Tp[e] + Tp[e + 4096] + Tp[e + 8192] + Tp[e + 12288];
        T_s[(e >> 6) * TPADF + (e & 63)] = s;
    }

    for (int ch = 0; ch < 4; ch++) {
        int j0 = slice * 256 + ch * 64;
        cp_wait<0>();
        __syncthreads();
        if (ch + 1 < 4) load_w((ch + 1) & 1, slice * 256 + (ch + 1) * 64);
        cp_commit();

        const float* W_s = (const float*)(dsm + U_MAT + (ch & 1) * U_MAT);
        float acc[4][4] = {};
#pragma unroll 8
        for (int r = 0; r < 64; r++) {
            float4 tr4 = *(const float4*)&T_s[r * TPADF + ti * 4];
            float4 wr4 = *(const float4*)&W_s[r * TPADF + tj * 4];
            float tr[4] = {tr4.x, tr4.y, tr4.z, tr4.w};
            float wr[4] = {wr4.x, wr4.y, wr4.z, wr4.w};
#pragma unroll
            for (int i = 0; i < 4; i++)
#pragma unroll
                for (int j = 0; j < 4; j++)
                    acc[i][j] = fmaf(tr[i], wr[j], acc[i][j]);
        }
#pragma unroll
        for (int i = 0; i < 4; i++) {
            int c = ti * 4 + i;
            size_t off = (size_t)b * DD_ + (size_t)(h * 64 + c) * D_ + j0 + tj * 4;
#pragma unroll
            for (int j = 0; j < 4; j += 2) {
                *(__half2*)(&g_UhT[off + j]) = __halves2half2(
                    __float2half_rn(acc[i][j] * 0.125f),
                    __float2half_rn(acc[i][j + 1] * 0.125f));
            }
        }
        __syncthreads();
    }
}

// ---------------------------------------------------------------------------
// Kernel: mask correction (int4-vectorized fast scan; generic slow path)
// ---------------------------------------------------------------------------
__global__ __launch_bounds__(256) void mask_fix(const float* __restrict__ x,
                                                const float* __restrict__ wq,
                                                const float* __restrict__ wk,
                                                const float* __restrict__ wv,
                                                const int* __restrict__ mask,
                                                float* __restrict__ out)
{
    int bq = blockIdx.x;
    int b  = bq >> 11;
    const int* mrow = mask + (size_t)bq * S_;

    const int4* m4 = (const int4*)mrow;
    bool zf = false;
#pragma unroll
    for (int it = 0; it < 2; it++) {
        int4 v = m4[threadIdx.x + it * 256];
        zf |= (v.x == 0) | (v.y == 0) | (v.z == 0) | (v.w == 0);
    }
    if (!__syncthreads_or(zf)) return;

    // ---- slow path (generic correctness; not exercised by all-ones mask) ----
    __shared__ float xq[1024], qv[1024], xkb[1024], kv[1024], vvv[1024], sc[16];
    const float* xrow = x + (size_t)bq * D_;
    for (int i = threadIdx.x; i < 1024; i += 256) xq[i] = xrow[i];
    __syncthreads();
    for (int i = threadIdx.x; i < 1024; i += 256) {
        float a = 0.f;
        const float* wr = wq + (size_t)i * D_;
        for (int t = 0; t < 1024; t++) a += xq[t] * wr[t];
        qv[i] = a;
    }
    __syncthreads();

    for (int k = 0; k < S_; k++) {
        if (mrow[k] != 0) continue;
        const float* xk = x + ((size_t)b * S_ + k) * D_;
        for (int i = threadIdx.x; i < 1024; i += 256) xkb[i] = xk[i];
        __syncthreads();
        for (int i = threadIdx.x; i < 1024; i += 256) {
            float a = 0.f, c = 0.f;
            const float* wrk = wk + (size_t)i * D_;
            const float* wrv = wv + (size_t)i * D_;
            for (int t = 0; t < 1024; t++) {
                float xv = xkb[t];
                a += xv * wrk[t];
                c += xv * wrv[t];
            }
            kv[i] = a; vvv[i] = c;
        }
        __syncthreads();
        if (threadIdx.x < 16) {
            int h = threadIdx.x;
            float s = 0.f;
            for (int r = 0; r < 64; r++) s += qv[h * 64 + r] * kv[h * 64 + r];
            sc[h] = s * 0.125f;
        }
        __syncthreads();
        float* orow = out + (size_t)bq * D_;
        for (int i = threadIdx.x; i < 1024; i += 256)
            orow[i] += (-1e9f - sc[i >> 6]) * vvv[i];
        __syncthreads();
    }
}

// ---------------------------------------------------------------------------
// Entry point
// ---------------------------------------------------------------------------
extern "C" void kernel_launch(void* const* d_in, const int* in_sizes, int n_in,
                              void* d_out, int out_size)
{
    const float* x    = (const float*)d_in[0];
    const int*   mask = (const int*)  d_in[1];
    const float* wq   = (const float*)d_in[2];
    const float* wk   = (const float*)d_in[3];
    const float* wv   = (const float*)d_in[4];
    float*       out  = (float*)d_out;

    // DEVICE addresses of __device__ globals (never pass host shadow symbols).
    void *p_xh, *p_wvh, *p_ghh, *p_ah, *p_uhT;
    cudaGetSymbolAddress(&p_xh,  g_Xh);
    cudaGetSymbolAddress(&p_wvh, g_Wvh);
    cudaGetSymbolAddress(&p_ghh, g_Ghh);
    cudaGetSymbolAddress(&p_ah,  g_Ah);
    cudaGetSymbolAddress(&p_uhT, g_UhT);

    const __half* d_xh  = (const __half*)p_xh;
    const __half* d_wvh = (const __half*)p_wvh;
    __half*       d_ghh = (__half*)p_ghh;
    __half*       d_ah  = (__half*)p_ah;
    __half*       d_uhT = (__half*)p_uhT;

    cudaFuncSetAttribute(gram_sym,
        cudaFuncAttributeMaxDynamicSharedMemorySize, G_SMEM);
    cudaFuncSetAttribute(hgemm_bt<true>,
        cudaFuncAttributeMaxDynamicSharedMemorySize, BT_SMEM);
    cudaFuncSetAttribute(hgemm_bt<false>,
        cudaFuncAttributeMaxDynamicSharedMemorySize, BT_SMEM);
    cudaFuncSetAttribute(t_kernel3,
        cudaFuncAttributeMaxDynamicSharedMemorySize, T_SMEM);
    cudaFuncSetAttribute(u_kernel3,
        cudaFuncAttributeMaxDynamicSharedMemorySize, U_SMEM);

    // 0) fused prep: X fp16 (+transpose) and Wv fp16 in one launch
    prep_all<<<dim3(16, 32, 5), 256>>>(x, wv);

    // 1) Symmetric Gram: Ghh_b = fp16(Xh_b^T @ Xh_b), 144 CTAs = 1 wave
    gram_sym<<<dim3(36, 1, 4), 256, G_SMEM>>>();

    // 2) A_b = Ghh_b @ Wvh^T  (M=1024, N=1024, K=1024), fp16 output
    hgemm_bt<true><<<dim3(4, 8, 4), 256, BT_SMEM>>>(
        d_ghh, d_wvh, (float*)nullptr, d_ah,
        1024, 1024, 1024, 1024,
        DD_, 0, DD_);

    // 3) T partials (A fp16 in) + U^T, cp.async-pipelined
    t_kernel3<<<dim3(B_ * H_, 4), 256, T_SMEM>>>(wk);
    u_kernel3<<<dim3(B_ * H_, 4), 256, U_SMEM>>>(wq);

    // 4) out_b = Xh_b @ Uh_b  (M=2048, N=1024, K=1024), writes d_out
    hgemm_bt<false><<<dim3(4, 16, 4), 256, BT_SMEM>>>(
        d_xh, d_uhT, out, (__half*)nullptr,
        1024, 1024, 1024, 1024,
        (size_t)2048 * D_, DD_, (size_t)2048 * D_);

    // 5) generic mask handling
    mask_fix<<<B_ * S_, 256>>>(x, wq, wk, wv, mask, out);
}